// round 12
// baseline (speedup 1.0000x reference)
#include <cuda_runtime.h>
#include <cuda_fp16.h>
#include <stdint.h>

// Problem constants
#define BB 2
#define NN 16384
#define KK 32
#define FF 64
#define EE 16
#define NT (BB * NN)      // 32768 nodes
#define SK (FF * EE)      // 1024 = GEMM contraction length

// Scratch (static __device__ arrays — no runtime allocation)
// g_Sf: S in HMMA A-fragment-major layout:
//   uint2 index = tile*4096 + ktile*64 + half*32 + row*4 + q
//   (tile = node/16, half: rows 0-7 / 8-15, ktile = l, q = n-quad)
__device__ __align__(16) __half g_Sf[(size_t)NT * SK];  // 64 MB
__device__ __align__(16) __half g_B[FF * SK];           // B[n][k] = w2^T (fp16)
__device__ __align__(16) __half g_Gh[(size_t)NT * FF];  // 4 MB: nodes in fp16

static __device__ __forceinline__ uint32_t hfpack(float hi, float lo) {
    uint32_t r;
    asm("cvt.rn.f16x2.f32 %0, %1, %2;" : "=r"(r) : "f"(hi), "f"(lo));
    return r;
}
static __device__ __forceinline__ uint32_t smem_u32(const void* p) {
    uint32_t a;
    asm("{ .reg .u64 t; cvta.to.shared.u64 t, %1; cvt.u32.u64 %0, t; }" : "=r"(a) : "l"(p));
    return a;
}
static __device__ __forceinline__ void ldsm4(uint32_t* r, uint32_t addr) {
    asm volatile("ldmatrix.sync.aligned.m8n8.x4.shared.b16 {%0,%1,%2,%3}, [%4];"
                 : "=r"(r[0]), "=r"(r[1]), "=r"(r[2]), "=r"(r[3]) : "r"(addr));
}
static __device__ __forceinline__ void ldsm4t(uint32_t* r, uint32_t addr) {
    asm volatile("ldmatrix.sync.aligned.m8n8.x4.trans.shared.b16 {%0,%1,%2,%3}, [%4];"
                 : "=r"(r[0]), "=r"(r[1]), "=r"(r[2]), "=r"(r[3]) : "r"(addr));
}
static __device__ __forceinline__ void mma16816h(float* c, const uint32_t* a,
                                                 const uint32_t* b) {
    asm volatile(
        "mma.sync.aligned.m16n8k16.row.col.f32.f16.f16.f32 "
        "{%0,%1,%2,%3}, {%4,%5,%6,%7}, {%8,%9}, {%0,%1,%2,%3};"
        : "+f"(c[0]), "+f"(c[1]), "+f"(c[2]), "+f"(c[3])
        : "r"(a[0]), "r"(a[1]), "r"(a[2]), "r"(a[3]), "r"(b[0]), "r"(b[1]));
}

// ---- kernel 0: nodes -> fp16 (g_Gh) + W2 transpose -> g_B (fp16), 4x MLP ----
__global__ __launch_bounds__(256) void k_conv(
    const float* __restrict__ nodes, const float* __restrict__ w)
{
    int base = blockIdx.x * 1024 + threadIdx.x;      // 512 blocks
    float4 v[4];
#pragma unroll
    for (int i = 0; i < 4; i++)
        v[i] = reinterpret_cast<const float4*>(nodes)[base + i * 256];
#pragma unroll
    for (int i = 0; i < 4; i++)
        reinterpret_cast<uint2*>(g_Gh)[base + i * 256] =
            make_uint2(hfpack(v[i].y, v[i].x), hfpack(v[i].w, v[i].z));
    if (blockIdx.x < 64) {                           // W: 64 blocks x 1024 ids
#pragma unroll
        for (int i = 0; i < 4; i++) {
            int id = base + i * 256;                 // id = n*1024 + k
            int n = id >> 10;
            int k = id & 1023;
            int l = k >> 4;
            int e = k & 15;
            g_B[id] = __float2half(w[l * (FF * EE) + n * EE + e]);
        }
    }
}

// ---- kernel 1 (tensor): per node, S[64l][16n] = sum_j G[j][l] * (E[j][n]/32) ----
// One warp per node; single-product fp16 HMMA; epilogue stores C fragments
// DIRECTLY into g_Sf's A-fragment layout (8 STG.64/lane, 32B-sector exact).
#define S1NODES 8
#define GP 144                    // G row pitch bytes
#define EP 48                     // E row pitch bytes
#define GBYTES (32 * GP)          // 4608
#define EBYTES (32 * EP)          // 1536
#define NODE_SM (GBYTES + EBYTES)           // 6144
#define S1SMEM (S1NODES * NODE_SM)          // 49152

__global__ __launch_bounds__(256) void k_stage1(
    const int*   __restrict__ nlist,
    const float* __restrict__ edges)
{
    extern __shared__ __align__(16) char sm1[];
    const int t    = threadIdx.x;
    const int warp = t >> 5;
    const int lane = t & 31;
    const int g    = blockIdx.x * S1NODES + warp;
    const int b    = g >> 14;

    char* base = sm1 + warp * NODE_SM;
    const uint32_t sb = smem_u32(base);

    const int my_idx = nlist[(size_t)g * KK + lane];
    const __half* nbase = g_Gh + (size_t)b * (NN * FF);

    // gather G (fp16, 128B rows): 8 LDG.128 batched for MLP
    const int l4   = lane & 7;
    const int rsub = lane >> 3;
    {
        uint4 gv[8];
#pragma unroll
        for (int p = 0; p < 8; p++) {
            int j = p * 4 + rsub;
            int jdx = __shfl_sync(0xffffffffu, my_idx, j);
            gv[p] = *reinterpret_cast<const uint4*>(
                nbase + (size_t)jdx * FF + l4 * 8);
        }
#pragma unroll
        for (int p = 0; p < 8; p++)
            *reinterpret_cast<uint4*>(base + (p * 4 + rsub) * GP + l4 * 16) = gv[p];
    }
    // E: 32 x 16 fp32 -> fp16 with exact 1/32
    {
        const float4* ef = reinterpret_cast<const float4*>(edges) + (size_t)g * 128;
#pragma unroll
        for (int qq = 0; qq < 4; qq++) {
            int u = qq * 32 + lane;
            float4 v = ef[u];
            int j = u >> 2, n4 = u & 3;
            *reinterpret_cast<uint2*>(base + GBYTES + j * EP + n4 * 8) =
                make_uint2(hfpack(v.y * 0.03125f, v.x * 0.03125f),
                           hfpack(v.w * 0.03125f, v.z * 0.03125f));
        }
    }
    __syncwarp();

    // ldmatrix.trans fragment addresses (proven mappings)
    const uint32_t aA = sb + ((lane & 7) + 8 * (lane >> 4)) * GP
                           + ((lane >> 3) & 1) * 16;
    const uint32_t aB = sb + GBYTES
                           + ((lane & 7) + 8 * ((lane >> 3) & 1)) * EP
                           + (lane >> 4) * 16;

    float C[4][2][4];
#pragma unroll
    for (int mt = 0; mt < 4; mt++)
#pragma unroll
        for (int nt = 0; nt < 2; nt++)
#pragma unroll
            for (int i = 0; i < 4; i++) C[mt][nt][i] = 0.0f;

#pragma unroll
    for (int ks = 0; ks < 2; ks++) {
        uint32_t bh[4];
        ldsm4t(bh, aB + ks * 16 * EP);
#pragma unroll
        for (int mt = 0; mt < 4; mt++) {
            uint32_t ah[4];
            ldsm4t(ah, aA + ks * 16 * GP + mt * 32);
            mma16816h(C[mt][0], ah, bh);
            mma16816h(C[mt][1], ah, bh + 2);
        }
    }

    // ---- epilogue: direct A-fragment-layout stores ----
    // lane (r_l = lane>>2, q = lane&3): C[mt][nt] c0c1 are k-tile l = mt*16+r_l,
    // n = nt*8 + 2q (+1); c2c3 are l+8. uint2 = (nt0 word, nt1 word) lands at
    // consumer lane slot (node&7)*4 + q in half (g>>3)&1 of tile g>>4.
    {
        const int r_l = lane >> 2, q = lane & 3;
        uint2* Sf = reinterpret_cast<uint2*>(g_Sf);
        size_t basei = (size_t)(g >> 4) * 4096 + ((g >> 3) & 1) * 32
                     + (g & 7) * 4 + q;
#pragma unroll
        for (int mt = 0; mt < 4; mt++) {
            int kt = mt * 16 + r_l;
            Sf[basei + (size_t)kt * 64] =
                make_uint2(hfpack(C[mt][0][1], C[mt][0][0]),
                           hfpack(C[mt][1][1], C[mt][1][0]));
            Sf[basei + (size_t)(kt + 8) * 64] =
                make_uint2(hfpack(C[mt][0][3], C[mt][0][2]),
                           hfpack(C[mt][1][3], C[mt][1][2]));
        }
    }
}

// ---- kernel 2: HMMA GEMM out[32768 x 64] = S @ W2 ----
// M-tile 128, grid 256. Warps: 4 row-groups x 2 col-groups; warp = 32 rows x
// 32 cols. A fragments loaded DIRECTLY from g_Sf via 2 LDG.64 (no smem for A),
// software-pipelined one ktile ahead. B double-buffered in smem, 1 sync/chunk.
#define KC 64
#define BPITCH 144
#define BBUF (FF * BPITCH)                   // 9216
#define SMEM2_SZ (2 * BBUF)                  // 18432

__global__ __launch_bounds__(256) void k_stage2(float* __restrict__ out)
{
    extern __shared__ __align__(16) char sm[];
    const int t    = threadIdx.x;
    const int w    = t >> 5;
    const int lane = t & 31;
    const int wr   = w & 3;                  // row group (32 rows)
    const int wc   = w >> 2;                 // col group (32 cols)
    const int m0   = blockIdx.x * 128;
    const uint32_t smb = smem_u32(sm);

    const uint2* Sf = reinterpret_cast<const uint2*>(g_Sf);
    const size_t aBase0 = (size_t)(blockIdx.x * 8 + 2 * wr) * 4096 + lane;
    const size_t aBase1 = aBase0 + 4096;

    const uint32_t aBoff = (uint32_t)(wc * 32 + 8 * (lane >> 4) + (lane & 7)) * BPITCH
                         + ((lane >> 3) & 1) * 16;

    // B chunk 0 preload (64 n x 64 k = 8 KB; 2 uint4/thread)
    {
        uint4 rb[2];
#pragma unroll
        for (int q2 = 0; q2 < 2; q2++) {
            int u = t + q2 * 256;            // 0..511
            int n = u >> 3, j = u & 7;
            rb[q2] = *reinterpret_cast<const uint4*>(g_B + (size_t)n * SK + j * 8);
        }
#pragma unroll
        for (int q2 = 0; q2 < 2; q2++) {
            int u = t + q2 * 256;
            int n = u >> 3, j = u & 7;
            *reinterpret_cast<uint4*>(sm + n * BPITCH + j * 16) = rb[q2];
        }
    }
    __syncthreads();

    // A pipeline: preload ktile 0
    uint2 lo[2][2], hi[2][2];
    lo[0][0] = Sf[aBase0];      hi[0][0] = Sf[aBase0 + 32];
    lo[0][1] = Sf[aBase1];      hi[0][1] = Sf[aBase1 + 32];

    float acc[2][4][4];
#pragma unroll
    for (int s = 0; s < 2; s++)
#pragma unroll
        for (int nt = 0; nt < 4; nt++)
#pragma unroll
            for (int i = 0; i < 4; i++) acc[s][nt][i] = 0.0f;

    for (int c = 0; c < SK / KC; c++) {      // 16 chunks
        uint4 rb[2];
        if (c < 15) {
#pragma unroll
            for (int q2 = 0; q2 < 2; q2++) {
                int u = t + q2 * 256;
                int n = u >> 3, j = u & 7;
                rb[q2] = *reinterpret_cast<const uint4*>(
                    g_B + (size_t)n * SK + (c + 1) * KC + j * 8);
            }
        }
        const uint32_t buf = (uint32_t)(c & 1) * BBUF;
#pragma unroll
        for (int ks = 0; ks < 4; ks++) {
            const int kt  = c * 4 + ks;
            const int cur = ks & 1, nxt = cur ^ 1;
            if (kt < 63) {                   // prefetch next ktile's A
                size_t o = (size_t)(kt + 1) * 64;
                lo[nxt][0] = Sf[aBase0 + o];  hi[nxt][0] = Sf[aBase0 + o + 32];
                lo[nxt][1] = Sf[aBase1 + o];  hi[nxt][1] = Sf[aBase1 + o + 32];
            }
            uint32_t bf[4][2];
#pragma unroll
            for (int p = 0; p < 2; p++) {
                uint32_t r4[4];
                ldsm4(r4, smb + buf + aBoff + p * 16 * BPITCH + ks * 32);
                bf[2 * p][0] = r4[0]; bf[2 * p][1] = r4[1];
                bf[2 * p + 1][0] = r4[2]; bf[2 * p + 1][1] = r4[3];
            }
#pragma unroll
            for (int s = 0; s < 2; s++) {
                uint32_t a[4] = { lo[cur][s].x, hi[cur][s].x,
                                  lo[cur][s].y, hi[cur][s].y };
#pragma unroll
                for (int nt = 0; nt < 4; nt++)
                    mma16816h(acc[s][nt], a, bf[nt]);
            }
        }
        if (c < 15) {
#pragma unroll
            for (int q2 = 0; q2 < 2; q2++) {
                int u = t + q2 * 256;
                int n = u >> 3, j = u & 7;
                *reinterpret_cast<uint4*>(
                    sm + ((c + 1) & 1) * BBUF + n * BPITCH + j * 16) = rb[q2];
            }
        }
        __syncthreads();
    }

    // epilogue
    const int cb = 2 * (lane & 3);
#pragma unroll
    for (int s = 0; s < 2; s++) {
        const int row0 = m0 + wr * 32 + s * 16 + (lane >> 2);
#pragma unroll
        for (int nt = 0; nt < 4; nt++) {
            int col = (wc * 4 + nt) * 8 + cb;
            *reinterpret_cast<float2*>(out + (size_t)row0 * FF + col) =
                make_float2(acc[s][nt][0], acc[s][nt][1]);
            *reinterpret_cast<float2*>(out + (size_t)(row0 + 8) * FF + col) =
                make_float2(acc[s][nt][2], acc[s][nt][3]);
        }
    }
}

extern "C" void kernel_launch(void* const* d_in, const int* in_sizes, int n_in,
                              void* d_out, int out_size) {
    const float* nodes = (const float*)d_in[0];
    const int*   nlist = (const int*)d_in[1];
    const float* edges = (const float*)d_in[2];
    const float* w     = (const float*)d_in[3];
    float* out = (float*)d_out;
    (void)in_sizes; (void)n_in; (void)out_size;

    cudaFuncSetAttribute(k_stage1,
                         cudaFuncAttributeMaxDynamicSharedMemorySize, S1SMEM);
    cudaFuncSetAttribute(k_stage2,
                         cudaFuncAttributeMaxDynamicSharedMemorySize, SMEM2_SZ);

    k_conv<<<NT * FF / 4 / 1024, 256>>>(nodes, w);
    k_stage1<<<NT / S1NODES, 256, S1SMEM>>>(nlist, edges);
    k_stage2<<<NT / 128, 256, SMEM2_SZ>>>(out);
}

// round 13
// speedup vs baseline: 1.3303x; 1.3303x over previous
#include <cuda_runtime.h>
#include <cuda_fp16.h>
#include <stdint.h>

// Problem constants
#define BB 2
#define NN 16384
#define KK 32
#define FF 64
#define EE 16
#define NT (BB * NN)      // 32768 nodes
#define SK (FF * EE)      // 1024 = GEMM contraction length

// Scratch (static __device__ arrays — no runtime allocation)
__device__ __align__(16) __half g_S[(size_t)NT * SK];   // 64 MB: S (fp16)
__device__ __align__(16) __half g_B[FF * SK];           // B[n][k] = w2^T (fp16)
__device__ __align__(16) __half g_Gh[(size_t)NT * FF];  // 4 MB: nodes in fp16

static __device__ __forceinline__ uint32_t hfpack(float hi, float lo) {
    uint32_t r;
    asm("cvt.rn.f16x2.f32 %0, %1, %2;" : "=r"(r) : "f"(hi), "f"(lo));
    return r;
}
static __device__ __forceinline__ uint32_t smem_u32(const void* p) {
    uint32_t a;
    asm("{ .reg .u64 t; cvta.to.shared.u64 t, %1; cvt.u32.u64 %0, t; }" : "=r"(a) : "l"(p));
    return a;
}
static __device__ __forceinline__ void ldsm4(uint32_t* r, uint32_t addr) {
    asm volatile("ldmatrix.sync.aligned.m8n8.x4.shared.b16 {%0,%1,%2,%3}, [%4];"
                 : "=r"(r[0]), "=r"(r[1]), "=r"(r[2]), "=r"(r[3]) : "r"(addr));
}
static __device__ __forceinline__ void ldsm4t(uint32_t* r, uint32_t addr) {
    asm volatile("ldmatrix.sync.aligned.m8n8.x4.trans.shared.b16 {%0,%1,%2,%3}, [%4];"
                 : "=r"(r[0]), "=r"(r[1]), "=r"(r[2]), "=r"(r[3]) : "r"(addr));
}
static __device__ __forceinline__ void mma16816h(float* c, const uint32_t* a,
                                                 const uint32_t* b) {
    asm volatile(
        "mma.sync.aligned.m16n8k16.row.col.f32.f16.f16.f32 "
        "{%0,%1,%2,%3}, {%4,%5,%6,%7}, {%8,%9}, {%0,%1,%2,%3};"
        : "+f"(c[0]), "+f"(c[1]), "+f"(c[2]), "+f"(c[3])
        : "r"(a[0]), "r"(a[1]), "r"(a[2]), "r"(a[3]), "r"(b[0]), "r"(b[1]));
}
static __device__ __forceinline__ void cpa16(uint32_t dst, const void* src) {
    asm volatile("cp.async.cg.shared.global [%0], [%1], 16;"
                 :: "r"(dst), "l"(src) : "memory");
}
#define CP_COMMIT() asm volatile("cp.async.commit_group;" ::: "memory")
#define CP_WAIT(n)  asm volatile("cp.async.wait_group %0;" :: "n"(n) : "memory")

// ---- kernel 0: nodes -> fp16 (g_Gh) + W2 transpose -> g_B (fp16) ----
__global__ __launch_bounds__(256) void k_conv(
    const float* __restrict__ nodes, const float* __restrict__ w)
{
    int t = blockIdx.x * 256 + threadIdx.x;          // 0 .. 524287
    float4 v = reinterpret_cast<const float4*>(nodes)[t];
    reinterpret_cast<uint2*>(g_Gh)[t] =
        make_uint2(hfpack(v.y, v.x), hfpack(v.w, v.z));
    if (t < FF * SK) {                               // id = n*1024 + k
        int n = t >> 10;
        int k = t & 1023;
        int l = k >> 4;
        int e = k & 15;
        g_B[t] = __float2half(w[l * (FF * EE) + n * EE + e]);
    }
}

// ---- kernel 1 (tensor): per node, S[64l][16n] = sum_j G[j][l] * (E[j][n]/32) ----
// One warp per node; E (DRAM) loads issued before G (L2) gather for max MLP.
#define S1NODES 8
#define GP 144                    // G row pitch bytes
#define EP 48                     // E row pitch bytes
#define GBYTES (32 * GP)          // 4608
#define EBYTES (32 * EP)          // 1536
#define NODE_SM (GBYTES + EBYTES)           // 6144
#define S1SMEM (S1NODES * NODE_SM)          // 49152

__global__ __launch_bounds__(256) void k_stage1(
    const int*   __restrict__ nlist,
    const float* __restrict__ edges)
{
    extern __shared__ __align__(16) char sm1[];
    const int t    = threadIdx.x;
    const int warp = t >> 5;
    const int lane = t & 31;
    const int g    = blockIdx.x * S1NODES + warp;
    const int b    = g >> 14;

    char* base = sm1 + warp * NODE_SM;
    const uint32_t sb = smem_u32(base);

    const int my_idx = nlist[(size_t)g * KK + lane];
    const __half* nbase = g_Gh + (size_t)b * (NN * FF);
    const int l4   = lane & 7;
    const int rsub = lane >> 3;

    // E loads first (DRAM, longest latency), then gather (L2): 12 outstanding
    float4 ev[4];
    {
        const float4* ef = reinterpret_cast<const float4*>(edges) + (size_t)g * 128;
#pragma unroll
        for (int qq = 0; qq < 4; qq++) ev[qq] = ef[qq * 32 + lane];
    }
    uint4 gv[8];
#pragma unroll
    for (int p = 0; p < 8; p++) {
        int j = p * 4 + rsub;
        int jdx = __shfl_sync(0xffffffffu, my_idx, j);
        gv[p] = *reinterpret_cast<const uint4*>(nbase + (size_t)jdx * FF + l4 * 8);
    }
#pragma unroll
    for (int p = 0; p < 8; p++)
        *reinterpret_cast<uint4*>(base + (p * 4 + rsub) * GP + l4 * 16) = gv[p];
#pragma unroll
    for (int qq = 0; qq < 4; qq++) {
        int u = qq * 32 + lane;
        int j = u >> 2, n4 = u & 3;
        *reinterpret_cast<uint2*>(base + GBYTES + j * EP + n4 * 8) =
            make_uint2(hfpack(ev[qq].y * 0.03125f, ev[qq].x * 0.03125f),
                       hfpack(ev[qq].w * 0.03125f, ev[qq].z * 0.03125f));
    }
    __syncwarp();

    // ldmatrix.trans fragment addresses (proven mappings)
    const uint32_t aA = sb + ((lane & 7) + 8 * (lane >> 4)) * GP
                           + ((lane >> 3) & 1) * 16;
    const uint32_t aB = sb + GBYTES
                           + ((lane & 7) + 8 * ((lane >> 3) & 1)) * EP
                           + (lane >> 4) * 16;

    float C[4][2][4];
#pragma unroll
    for (int mt = 0; mt < 4; mt++)
#pragma unroll
        for (int nt = 0; nt < 2; nt++)
#pragma unroll
            for (int i = 0; i < 4; i++) C[mt][nt][i] = 0.0f;

#pragma unroll
    for (int ks = 0; ks < 2; ks++) {
        uint32_t bh[4];
        ldsm4t(bh, aB + ks * 16 * EP);
#pragma unroll
        for (int mt = 0; mt < 4; mt++) {
            uint32_t ah[4];
            ldsm4t(ah, aA + ks * 16 * GP + mt * 32);
            mma16816h(C[mt][0], ah, bh);
            mma16816h(C[mt][1], ah, bh + 2);
        }
    }

    // epilogue: pack fp16, stage in smem (reuse G region), coalesced STG.128
    __syncwarp();
    __half* sstage = reinterpret_cast<__half*>(base);
    const int r = lane >> 2, q = lane & 3;
#pragma unroll
    for (int mt = 0; mt < 4; mt++) {
#pragma unroll
        for (int nt = 0; nt < 2; nt++) {
            int k0 = (mt * 16 + r) * 16 + nt * 8 + 2 * q;       // (c0,c1)
            *reinterpret_cast<uint32_t*>(sstage + k0) =
                hfpack(C[mt][nt][1], C[mt][nt][0]);
            *reinterpret_cast<uint32_t*>(sstage + k0 + 128) =
                hfpack(C[mt][nt][3], C[mt][nt][2]);
        }
    }
    __syncwarp();
    {
        uint4* dst = reinterpret_cast<uint4*>(g_S + (size_t)g * SK);
        const uint4* src = reinterpret_cast<const uint4*>(sstage);
#pragma unroll
        for (int u = 0; u < 4; u++)
            dst[u * 32 + lane] = src[u * 32 + lane];
    }
}

// ---- kernel 2: HMMA GEMM out[32768 x 64] = S(fp16) @ W2(fp16) ----
// M-tile 128, grid 256. cp.async double-buffered A+B staging: chunk c+1's copy
// overlaps chunk c's MMAs. Warps: 4 row-groups x 2 col-groups (32r x 32c each).
#define KC 64
#define PIT 144
#define SA0 0
#define SA1 (128 * PIT)                      // 18432
#define SB0 (2 * 128 * PIT)                  // 36864
#define SB1 (SB0 + 64 * PIT)                 // 46080
#define SMEM2_SZ (SB1 + 64 * PIT)            // 55296

__global__ __launch_bounds__(256) void k_stage2(float* __restrict__ out)
{
    extern __shared__ __align__(16) char sm[];
    const int t    = threadIdx.x;
    const int w    = t >> 5;
    const int lane = t & 31;
    const int wr   = w & 3;                  // row group (32 rows)
    const int wc   = w >> 2;                 // col group (32 cols)
    const int m0   = blockIdx.x * 128;
    const uint32_t smb = smem_u32(sm);

    const int ar = t >> 3;                   // 0..31
    const int aj = t & 7;

    const int a_r = (lane & 7) + ((lane >> 3) & 1) * 8;
    const int a_k = (lane >> 4) * 8;
    const uint32_t aAoff = (uint32_t)(wr * 32 + a_r) * PIT + a_k * 2;
    const uint32_t aBoff = (uint32_t)(wc * 32 + 8 * (lane >> 4) + (lane & 7)) * PIT
                         + ((lane >> 3) & 1) * 16;

    // cp.async issue for chunk c into buffer c&1
    auto issue = [&](int c) {
        const int kk = c * KC;
        const uint32_t bufA = smb + ((c & 1) ? SA1 : SA0);
        const uint32_t bufB = smb + ((c & 1) ? SB1 : SB0);
#pragma unroll
        for (int qq = 0; qq < 4; qq++) {
            int row = ar + 32 * qq;
            cpa16(bufA + row * PIT + aj * 16,
                  g_S + (size_t)(m0 + row) * SK + kk + aj * 8);
        }
#pragma unroll
        for (int q2 = 0; q2 < 2; q2++) {
            int u = t + q2 * 256;            // 0..511
            int n = u >> 3, j = u & 7;
            cpa16(bufB + n * PIT + j * 16, g_B + (size_t)n * SK + kk + j * 8);
        }
        CP_COMMIT();
    };

    float acc[2][4][4];
#pragma unroll
    for (int s = 0; s < 2; s++)
#pragma unroll
        for (int nt = 0; nt < 4; nt++)
#pragma unroll
            for (int i = 0; i < 4; i++) acc[s][nt][i] = 0.0f;

    issue(0);
    for (int c = 0; c < SK / KC; c++) {      // 16 chunks
        if (c < 15) { issue(c + 1); CP_WAIT(1); }
        else        { CP_WAIT(0); }
        __syncthreads();

        const uint32_t bufA = smb + ((c & 1) ? SA1 : SA0);
        const uint32_t bufB = smb + ((c & 1) ? SB1 : SB0);
#pragma unroll
        for (int ks = 0; ks < 4; ks++) {
            const int kb2 = ks * 32;
            uint32_t a0[4], a1[4];
            ldsm4(a0, bufA + aAoff + kb2);
            ldsm4(a1, bufA + aAoff + 16 * PIT + kb2);
            uint32_t bf[4][2];
#pragma unroll
            for (int p = 0; p < 2; p++) {
                uint32_t r4[4];
                ldsm4(r4, bufB + aBoff + p * 16 * PIT + kb2);
                bf[2 * p][0] = r4[0]; bf[2 * p][1] = r4[1];
                bf[2 * p + 1][0] = r4[2]; bf[2 * p + 1][1] = r4[3];
            }
#pragma unroll
            for (int nt = 0; nt < 4; nt++) {
                mma16816h(acc[0][nt], a0, bf[nt]);
                mma16816h(acc[1][nt], a1, bf[nt]);
            }
        }
        __syncthreads();                     // buffer reuse guard
    }

    // epilogue
    const int cb = 2 * (lane & 3);
#pragma unroll
    for (int s = 0; s < 2; s++) {
        const int row0 = m0 + wr * 32 + s * 16 + (lane >> 2);
#pragma unroll
        for (int nt = 0; nt < 4; nt++) {
            int col = (wc * 4 + nt) * 8 + cb;
            *reinterpret_cast<float2*>(out + (size_t)row0 * FF + col) =
                make_float2(acc[s][nt][0], acc[s][nt][1]);
            *reinterpret_cast<float2*>(out + (size_t)(row0 + 8) * FF + col) =
                make_float2(acc[s][nt][2], acc[s][nt][3]);
        }
    }
}

extern "C" void kernel_launch(void* const* d_in, const int* in_sizes, int n_in,
                              void* d_out, int out_size) {
    const float* nodes = (const float*)d_in[0];
    const int*   nlist = (const int*)d_in[1];
    const float* edges = (const float*)d_in[2];
    const float* w     = (const float*)d_in[3];
    float* out = (float*)d_out;
    (void)in_sizes; (void)n_in; (void)out_size;

    cudaFuncSetAttribute(k_stage1,
                         cudaFuncAttributeMaxDynamicSharedMemorySize, S1SMEM);
    cudaFuncSetAttribute(k_stage2,
                         cudaFuncAttributeMaxDynamicSharedMemorySize, SMEM2_SZ);

    k_conv<<<NT * FF / 4 / 256, 256>>>(nodes, w);
    k_stage1<<<NT / S1NODES, 256, S1SMEM>>>(nlist, edges);
    k_stage2<<<NT / 128, 256, SMEM2_SZ>>>(out);
}